// round 1
// baseline (speedup 1.0000x reference)
#include <cuda_runtime.h>
#include <math.h>
#include <stdint.h>

// Problem dims
#define Bz   256
#define Nn   196
#define Dd   1024
#define HID  1024
#define ATT  256
#define SIN  1024
#define WID  1024
#define ISD  256
#define Ss   10
#define G4   (4*HID)

// ---------------- device scratch (no runtime allocs allowed) ----------------
__device__ float g_vea[(size_t)Bz*Nn*ATT];   // vis_enc_att  [B,N,ATT]  ~51MB
__device__ float g_h[2][Bz*HID];
__device__ float g_c[Bz*HID];
__device__ float g_dec[Bz*ATT];
__device__ float g_logits[Bz*Nn];
__device__ float g_attout[Bz*Dd];
__device__ float g_ctx[Bz*SIN];
__device__ float g_gates[(size_t)Bz*G4];
__device__ float g_ppre[Bz*ISD];

// ---------------- helpers ----------------
__device__ __forceinline__ float tanha(float x) {
    float y;
    asm("tanh.approx.f32 %0, %1;" : "=f"(y) : "f"(x));
    return y;
}
__device__ __forceinline__ float sigmoidf_(float x) {
    return 1.0f / (1.0f + expf(-x));
}

// ---------------- generic dual-source GEMM ----------------
// C[m, n] = act( sum_k A1[m,k]*W1[n,k] (+ sum_k A2[m,k]*W2[n,k]) + b1[n] (+ b2[n]) )
// A row-major [M,K], W row-major [N,K] (PyTorch Linear layout), C row-major ld=ldC.
// ACT: 0 = none, 1 = tanh (accurate)
template<int BM, int BN, int BK, int TM, int TN, int ACT>
__global__ void __launch_bounds__(256)
gemm_dual(const float* __restrict__ A1, const float* __restrict__ W1, int K1,
          const float* __restrict__ A2, const float* __restrict__ W2, int K2,
          const float* __restrict__ b1, const float* __restrict__ b2,
          float* __restrict__ C, int ldC)
{
    __shared__ float As[BK][BM + 1];
    __shared__ float Ws[BK][BN + 1];
    constexpr int NT = (BM / TM) * (BN / TN);   // must be 256
    const int tx = threadIdx.x;
    const int m0 = blockIdx.y * BM;
    const int n0 = blockIdx.x * BN;
    const int tm = (tx / (BN / TN)) * TM;
    const int tn = (tx % (BN / TN)) * TN;

    float acc[TM][TN];
    #pragma unroll
    for (int i = 0; i < TM; i++)
        #pragma unroll
        for (int j = 0; j < TN; j++) acc[i][j] = 0.f;

    #pragma unroll 1
    for (int src = 0; src < 2; ++src) {
        const float* A = src ? A2 : A1;
        const float* W = src ? W2 : W1;
        const int K = src ? K2 : K1;
        if (A == nullptr) break;
        #pragma unroll 1
        for (int k0 = 0; k0 < K; k0 += BK) {
            // load A tile (BM x BK) transposed into As[k][m]
            constexpr int AV = (BM * BK / 4) / NT;   // float4 loads per thread
            #pragma unroll
            for (int t = 0; t < AV; t++) {
                int i = tx + t * NT;
                int row = i / (BK / 4);
                int kc  = (i % (BK / 4)) * 4;
                float4 v = *reinterpret_cast<const float4*>(A + (size_t)(m0 + row) * K + k0 + kc);
                As[kc + 0][row] = v.x; As[kc + 1][row] = v.y;
                As[kc + 2][row] = v.z; As[kc + 3][row] = v.w;
            }
            constexpr int WV = (BN * BK / 4) / NT;
            #pragma unroll
            for (int t = 0; t < WV; t++) {
                int i = tx + t * NT;
                int row = i / (BK / 4);
                int kc  = (i % (BK / 4)) * 4;
                float4 v = *reinterpret_cast<const float4*>(W + (size_t)(n0 + row) * K + k0 + kc);
                Ws[kc + 0][row] = v.x; Ws[kc + 1][row] = v.y;
                Ws[kc + 2][row] = v.z; Ws[kc + 3][row] = v.w;
            }
            __syncthreads();
            #pragma unroll
            for (int kk = 0; kk < BK; ++kk) {
                float ar[TM], wr[TN];
                #pragma unroll
                for (int i = 0; i < TM; i++) ar[i] = As[kk][tm + i];
                #pragma unroll
                for (int j = 0; j < TN; j++) wr[j] = Ws[kk][tn + j];
                #pragma unroll
                for (int i = 0; i < TM; i++)
                    #pragma unroll
                    for (int j = 0; j < TN; j++)
                        acc[i][j] = fmaf(ar[i], wr[j], acc[i][j]);
            }
            __syncthreads();
        }
    }

    #pragma unroll
    for (int i = 0; i < TM; i++) {
        #pragma unroll
        for (int j = 0; j < TN; j++) {
            int n = n0 + tn + j;
            float v = acc[i][j];
            if (b1) v += b1[n];
            if (b2) v += b2[n];
            if (ACT == 1) v = tanhf(v);
            C[(size_t)(m0 + tm + i) * ldC + n] = v;
        }
    }
}

// ---------------- attention: logits[b,n] = sum_a tanh(vea+dec)*w + fb ----------------
__global__ void __launch_bounds__(256)
att_logits_kernel(const float* __restrict__ vea, const float* __restrict__ dec,
                  const float* __restrict__ faw, const float* __restrict__ fab,
                  float* __restrict__ logits)
{
    const int b = blockIdx.x;
    __shared__ float sdec[ATT];
    __shared__ float sw[ATT];
    const int tx = threadIdx.x;
    sdec[tx] = dec[b * ATT + tx];
    sw[tx]   = faw[tx];
    __syncthreads();
    const int warp = tx >> 5, lane = tx & 31;
    const float bias = fab[0];
    for (int n = warp; n < Nn; n += 8) {
        const float* row = vea + ((size_t)b * Nn + n) * ATT;
        float s = 0.f;
        #pragma unroll
        for (int a0 = 0; a0 < ATT; a0 += 32) {
            int a = a0 + lane;
            s += tanha(row[a] + sdec[a]) * sw[a];
        }
        #pragma unroll
        for (int o = 16; o; o >>= 1) s += __shfl_xor_sync(0xffffffffu, s, o);
        if (lane == 0) logits[b * Nn + n] = s + bias;
    }
}

// ---------------- softmax over N + att_out = scores @ vis_enc ----------------
__global__ void __launch_bounds__(256)
softmax_attout_kernel(const float* __restrict__ logits, const float* __restrict__ vis,
                      float* __restrict__ attout)
{
    const int b = blockIdx.x;
    const int tx = threadIdx.x;
    __shared__ float sc[Nn];
    __shared__ float red[256];

    float v = (tx < Nn) ? logits[b * Nn + tx] : -INFINITY;
    red[tx] = v;
    __syncthreads();
    #pragma unroll
    for (int o = 128; o; o >>= 1) {
        if (tx < o) red[tx] = fmaxf(red[tx], red[tx + o]);
        __syncthreads();
    }
    float mx = red[0];
    __syncthreads();
    float e = (tx < Nn) ? expf(v - mx) : 0.f;
    red[tx] = e;
    __syncthreads();
    #pragma unroll
    for (int o = 128; o; o >>= 1) {
        if (tx < o) red[tx] += red[tx + o];
        __syncthreads();
    }
    float inv = 1.f / red[0];
    if (tx < Nn) sc[tx] = e * inv;
    __syncthreads();

    const float* base = vis + (size_t)b * Nn * Dd;
    const int d0 = tx * 4;
    float4 acc = make_float4(0.f, 0.f, 0.f, 0.f);
    #pragma unroll 4
    for (int n = 0; n < Nn; n++) {
        float s = sc[n];
        float4 x = *reinterpret_cast<const float4*>(base + (size_t)n * Dd + d0);
        acc.x = fmaf(s, x.x, acc.x);
        acc.y = fmaf(s, x.y, acc.y);
        acc.z = fmaf(s, x.z, acc.z);
        acc.w = fmaf(s, x.w, acc.w);
    }
    *reinterpret_cast<float4*>(attout + (size_t)b * Dd + d0) = acc;
}

// ---------------- LSTM elementwise ----------------
__global__ void __launch_bounds__(256)
lstm_kernel(const float* __restrict__ gates, float* __restrict__ c, float* __restrict__ hnew)
{
    const int idx = blockIdx.x * 256 + threadIdx.x;   // < B*HID
    const int b = idx / HID, hh = idx % HID;
    const float* gb = gates + (size_t)b * G4;
    float gi = gb[hh];
    float gf = gb[HID + hh];
    float gg = gb[2 * HID + hh];
    float go = gb[3 * HID + hh];
    float cn = sigmoidf_(gf) * c[idx] + sigmoidf_(gi) * tanhf(gg);
    c[idx] = cn;
    hnew[idx] = sigmoidf_(go) * tanhf(cn);
}

// ---------------- final stop head: p = ppre @ fw^T + fb ----------------
__global__ void __launch_bounds__(256)
stop_final_kernel(const float* __restrict__ ppre, const float* __restrict__ fw,
                  const float* __restrict__ fb, float* __restrict__ outp, int s)
{
    const int b = blockIdx.x;
    const int tx = threadIdx.x;   // 256 == ISD
    __shared__ float r0[256];
    __shared__ float r1[256];
    float v = ppre[b * ISD + tx];
    r0[tx] = v * fw[tx];
    r1[tx] = v * fw[ISD + tx];
    __syncthreads();
    #pragma unroll
    for (int o = 128; o; o >>= 1) {
        if (tx < o) { r0[tx] += r0[tx + o]; r1[tx] += r1[tx + o]; }
        __syncthreads();
    }
    if (tx == 0) {
        outp[(size_t)b * Ss * 2 + s * 2 + 0] = r0[0] + fb[0];
        outp[(size_t)b * Ss * 2 + s * 2 + 1] = r1[0] + fb[1];
    }
}

// ---------------- zero init h0, c ----------------
__global__ void zero2_kernel(float* __restrict__ a, float* __restrict__ b, int n)
{
    int i = blockIdx.x * 256 + threadIdx.x;
    if (i < n) { a[i] = 0.f; b[i] = 0.f; }
}

// ---------------- launch ----------------
extern "C" void kernel_launch(void* const* d_in, const int* in_sizes, int n_in,
                              void* d_out, int out_size)
{
    const float* vis        = (const float*)d_in[0];
    // d_in[1] = sentences (int64) — unused by the reference computation
    const float* enc_att_w  = (const float*)d_in[2];
    const float* enc_att_b  = (const float*)d_in[3];
    const float* dec_att_w  = (const float*)d_in[4];
    const float* dec_att_b  = (const float*)d_in[5];
    const float* full_att_w = (const float*)d_in[6];
    const float* full_att_b = (const float*)d_in[7];
    const float* ctx_w      = (const float*)d_in[8];
    const float* ctx_b      = (const float*)d_in[9];
    const float* W_ih       = (const float*)d_in[10];
    const float* b_ih       = (const float*)d_in[11];
    const float* W_hh       = (const float*)d_in[12];
    const float* b_hh       = (const float*)d_in[13];
    const float* topic_hid_w = (const float*)d_in[14];
    const float* topic_hid_b = (const float*)d_in[15];
    const float* topic_ctx_w = (const float*)d_in[16];
    const float* topic_ctx_b = (const float*)d_in[17];
    const float* stop_prev_w = (const float*)d_in[18];
    const float* stop_prev_b = (const float*)d_in[19];
    const float* stop_cur_w  = (const float*)d_in[20];
    const float* stop_cur_b  = (const float*)d_in[21];
    const float* final_stop_w = (const float*)d_in[22];
    const float* final_stop_b = (const float*)d_in[23];

    float* out = (float*)d_out;
    float* out_topics = out;                               // [B, S, WID]
    float* out_ps     = out + (size_t)Bz * Ss * WID;       // [B, S, 2]

    float *vea, *hbase, *c, *dec, *logits, *attout, *ctx, *gates, *ppre;
    cudaGetSymbolAddress((void**)&vea,    g_vea);
    cudaGetSymbolAddress((void**)&hbase,  g_h);
    cudaGetSymbolAddress((void**)&c,      g_c);
    cudaGetSymbolAddress((void**)&dec,    g_dec);
    cudaGetSymbolAddress((void**)&logits, g_logits);
    cudaGetSymbolAddress((void**)&attout, g_attout);
    cudaGetSymbolAddress((void**)&ctx,    g_ctx);
    cudaGetSymbolAddress((void**)&gates,  g_gates);
    cudaGetSymbolAddress((void**)&ppre,   g_ppre);
    float* h0 = hbase;
    float* h1 = hbase + Bz * HID;

    // zero h0 and c (deterministic per call)
    zero2_kernel<<<(Bz * HID + 255) / 256, 256>>>(h0, c, Bz * HID);

    // precompute vis_enc_att = vis_enc @ enc_att_w^T + b : [B*N, ATT]
    {
        dim3 grid(ATT / 64, (Bz * Nn) / 64);
        gemm_dual<64, 64, 32, 4, 4, 0><<<grid, 256>>>(
            vis, enc_att_w, Dd, nullptr, nullptr, 0,
            enc_att_b, nullptr, vea, ATT);
    }

    for (int s = 0; s < Ss; s++) {
        float* hc = (s & 1) ? h1 : h0;   // h (previous)
        float* hn = (s & 1) ? h0 : h1;   // h_new

        // dec = h @ dec_att_w^T + b : [B, ATT]
        gemm_dual<32, 32, 32, 2, 2, 0><<<dim3(ATT / 32, Bz / 32), 256>>>(
            hc, dec_att_w, HID, nullptr, nullptr, 0,
            dec_att_b, nullptr, dec, ATT);

        // logits
        att_logits_kernel<<<Bz, 256>>>(vea, dec, full_att_w, full_att_b, logits);

        // softmax + att_out
        softmax_attout_kernel<<<Bz, 256>>>(logits, vis, attout);

        // ctx = att_out @ ctx_w^T + b : [B, SIN]
        gemm_dual<64, 64, 32, 4, 4, 0><<<dim3(SIN / 64, Bz / 64), 256>>>(
            attout, ctx_w, Dd, nullptr, nullptr, 0,
            ctx_b, nullptr, ctx, SIN);

        // gates = ctx @ W_ih^T + b_ih + h @ W_hh^T + b_hh : [B, 4H]
        gemm_dual<64, 64, 32, 4, 4, 0><<<dim3(G4 / 64, Bz / 64), 256>>>(
            ctx, W_ih, SIN, hc, W_hh, HID,
            b_ih, b_hh, gates, G4);

        // LSTM elementwise -> c (in place), hn
        lstm_kernel<<<(Bz * HID) / 256, 256>>>(gates, c, hn);

        // topic = tanh(hn @ topic_hid^T + ctx @ topic_ctx^T + b1 + b2) -> out strided
        gemm_dual<64, 64, 32, 4, 4, 1><<<dim3(WID / 64, Bz / 64), 256>>>(
            hn, topic_hid_w, HID, ctx, topic_ctx_w, SIN,
            topic_hid_b, topic_ctx_b, out_topics + (size_t)s * WID, Ss * WID);

        // ppre = tanh(h_prev @ stop_prev^T + hn @ stop_cur^T + b1 + b2) : [B, ISD]
        gemm_dual<32, 32, 32, 2, 2, 1><<<dim3(ISD / 32, Bz / 32), 256>>>(
            hc, stop_prev_w, HID, hn, stop_cur_w, HID,
            stop_prev_b, stop_cur_b, ppre, ISD);

        // p = ppre @ final_stop_w^T + b -> out
        stop_final_kernel<<<Bz, 256>>>(ppre, final_stop_w, final_stop_b, out_ps, s);
    }
}